// round 16
// baseline (speedup 1.0000x reference)
#include <cuda_runtime.h>
#include <stdint.h>

#define BB 8
#define NN 16384
#define SS 2048
#define CC 64
#define KK 32
#define COUT (3 + CC)      // 67
#define NG2 (NN / 256)     // 64 iterations of 256 points

// Scratch (no cudaMalloc allowed).
__device__ __align__(16) int   g_idx[BB * SS * KK];
__device__ __align__(16) float g_px[BB * NN];
__device__ __align__(16) float g_py[BB * NN];
__device__ __align__(16) float g_pz[BB * NN];

__device__ __forceinline__ void cp_async16(uint32_t dst_smem, const void* src) {
    asm volatile("cp.async.cg.shared.global [%0], [%1], 16;\n"
                 :: "r"(dst_smem), "l"(src) : "memory");
}

// ---------------------------------------------------------------------------
// Kernel 0: AoS (B,N,3) -> SoA px/py/pz. 1024 blocks x 32 threads (128 points
// per block): ~7 blocks/SM so the LDG->LDS->STG chain latency overlaps.
// ---------------------------------------------------------------------------
__global__ __launch_bounds__(32) void transpose_kernel(
    const float4* __restrict__ pts4)    // (B*N*3)/4 float4s
{
    __shared__ float4 sm[96];           // 128 points * 3 floats
    const int tid = threadIdx.x;        // 0..31
    const int blk = blockIdx.x;         // 0..1023

    #pragma unroll
    for (int k = 0; k < 3; ++k)
        sm[tid + k * 32] = __ldg(pts4 + (size_t)blk * 96 + tid + k * 32);
    __syncwarp();

    const float* sf = (const float*)sm;
    const int lp = 12 * tid;            // local float base for points 4t..4t+3
    float4 vx, vy, vz;
    vx.x = sf[lp + 0]; vy.x = sf[lp + 1];  vz.x = sf[lp + 2];
    vx.y = sf[lp + 3]; vy.y = sf[lp + 4];  vz.y = sf[lp + 5];
    vx.z = sf[lp + 6]; vy.z = sf[lp + 7];  vz.z = sf[lp + 8];
    vx.w = sf[lp + 9]; vy.w = sf[lp + 10]; vz.w = sf[lp + 11];

    const int o = blk * 32 + tid;       // float4 index into SoA arrays
    ((float4*)g_px)[o] = vx;
    ((float4*)g_py)[o] = vy;
    ((float4*)g_pz)[o] = vz;
}

// ---------------------------------------------------------------------------
// Kernel 1: warp-per-center ball query over SoA points, 256 points/iter.
// NEW: nibble-packed hit counts + ONE shfl inclusive scan replace 8 ballots
// + 16 popc (positions identical: lane-major ascending order; low byte =
// sub0 count, high byte = sub1 count; cross-lane sums <= 128 so no carry).
// 6 coalesced LDG.128 prefetched one iteration ahead; exact (non-FMA) math;
// warp-uniform early exit. Index order: j = g*256 + sub*128 + 4*lane + c.
// Semantics: smallest 32 indices j with |c-p_j|^2 < 0.04 (ascending),
// padded with the first found index, or 0 if none found.
// ---------------------------------------------------------------------------
__global__ __launch_bounds__(256) void ball_query_kernel(
    const float* __restrict__ centers)   // (B, S, 3)
{
    const int wid  = threadIdx.x >> 5;
    const int lane = threadIdx.x & 31;
    const int gw   = blockIdx.x * 8 + wid;   // center id = b*S + s
    const int b    = gw / SS;

    const float* cptr = centers + (size_t)gw * 3;
    const float cx = __ldg(cptr + 0);
    const float cy = __ldg(cptr + 1);
    const float cz = __ldg(cptr + 2);

    __shared__ int sel[8][KK];

    const float4* px4 = (const float4*)(g_px + (size_t)b * NN);
    const float4* py4 = (const float4*)(g_py + (size_t)b * NN);
    const float4* pz4 = (const float4*)(g_pz + (size_t)b * NN);

    const float R2 = 0.04f;

    int cnt = 0;

    // prefetch iteration 0: f4 indices g*64 + lane (sub0) and +32 (sub1)
    float4 ax0 = __ldg(px4 + lane),      ay0 = __ldg(py4 + lane),      az0 = __ldg(pz4 + lane);
    float4 ax1 = __ldg(px4 + 32 + lane), ay1 = __ldg(py4 + 32 + lane), az1 = __ldg(pz4 + 32 + lane);

    for (int g = 0; g < NG2; ++g) {
        float4 bx0 = make_float4(0.f,0.f,0.f,0.f), by0 = bx0, bz0 = bx0;
        float4 bx1 = bx0, by1 = bx0, bz1 = bx0;
        if (g + 1 < NG2) {
            const int nf = (g + 1) * 64 + lane;
            bx0 = __ldg(px4 + nf);      by0 = __ldg(py4 + nf);      bz0 = __ldg(pz4 + nf);
            bx1 = __ldg(px4 + nf + 32); by1 = __ldg(py4 + nf + 32); bz1 = __ldg(pz4 + nf + 32);
        }

        float dx, dy, dz;
        #define DIST(PX,PY,PZ,DST)                                             \
            dx = __fadd_rn(cx, -(PX)); dy = __fadd_rn(cy, -(PY));              \
            dz = __fadd_rn(cz, -(PZ));                                         \
            DST = __fadd_rn(__fadd_rn(__fmul_rn(dx,dx), __fmul_rn(dy,dy)),     \
                            __fmul_rn(dz,dz));
        float q0,q1,q2,q3,q4,q5,q6,q7;
        DIST(ax0.x, ay0.x, az0.x, q0);
        DIST(ax0.y, ay0.y, az0.y, q1);
        DIST(ax0.z, ay0.z, az0.z, q2);
        DIST(ax0.w, ay0.w, az0.w, q3);
        DIST(ax1.x, ay1.x, az1.x, q4);
        DIST(ax1.y, ay1.y, az1.y, q5);
        DIST(ax1.z, ay1.z, az1.z, q6);
        DIST(ax1.w, ay1.w, az1.w, q7);
        #undef DIST

        // pack per-lane hit nibbles (bit c = point 4*lane+c of the sub-block)
        unsigned n0 = (q0 < R2 ? 1u : 0u) | (q1 < R2 ? 2u : 0u)
                    | (q2 < R2 ? 4u : 0u) | (q3 < R2 ? 8u : 0u);
        unsigned n1 = (q4 < R2 ? 1u : 0u) | (q5 < R2 ? 2u : 0u)
                    | (q6 < R2 ? 4u : 0u) | (q7 < R2 ? 8u : 0u);

        // packed counts: low byte = sub0, high byte = sub1 (sums <= 128)
        const unsigned v = (unsigned)__popc(n0) | ((unsigned)__popc(n1) << 8);
        unsigned s = v;
        #pragma unroll
        for (int o = 1; o < 32; o <<= 1) {
            const unsigned t = __shfl_up_sync(0xffffffffu, s, o);
            if (lane >= o) s += t;
        }
        const unsigned tot  = __shfl_sync(0xffffffffu, s, 31);
        const unsigned excl = s - v;            // byte-wise exclusive prefix
        const int t0 = (int)(tot & 0xFFu);
        const int t1 = (int)(tot >> 8);

        // sub0 hits: j = g*256 + 4*lane + c
        int p = cnt + (int)(excl & 0xFFu);
        const int j0 = g * 256 + 4 * lane;
        while (n0) {
            const int c = __ffs((int)n0) - 1; n0 &= n0 - 1u;
            if (p < KK) sel[wid][p] = j0 + c;
            p++;
        }
        // sub1 hits: j = g*256 + 128 + 4*lane + c (all > sub0 indices)
        int q = cnt + t0 + (int)(excl >> 8);
        const int j1 = j0 + 128;
        while (n1) {
            const int c = __ffs((int)n1) - 1; n1 &= n1 - 1u;
            if (q < KK) sel[wid][q] = j1 + c;
            q++;
        }

        cnt += t0 + t1;
        if (cnt >= KK) break;   // warp-uniform

        ax0 = bx0; ay0 = by0; az0 = bz0;
        ax1 = bx1; ay1 = by1; az1 = bz1;
    }
    __syncwarp();

    int v;
    if (cnt == 0) {
        v = 0;
    } else {
        const int first = sel[wid][0];
        v = (lane < cnt) ? sel[wid][lane] : first;
    }
    g_idx[(size_t)gw * KK + lane] = v;
}

// ---------------------------------------------------------------------------
// Kernel 2: gather (R9 best-measured config). Four chunks per (b, out-channel)
// plane, 512 threads. Stage 64KB row via cp.async, gather via LDS, coalesced
// float4 stores.
// ---------------------------------------------------------------------------
__global__ __launch_bounds__(512) void gather_kernel(
    const float* __restrict__ centers,  // (B, S, 3)
    const float* __restrict__ feats,    // (B, C, N)
    float* __restrict__ out)            // (B, 67, S, K)
{
    extern __shared__ float row[];      // NN floats = 64KB

    const int chunk = blockIdx.x;       // 0 .. B*67*4-1
    const int plane = chunk >> 2;
    const int quart = chunk & 3;
    const int b  = plane / COUT;
    const int co = plane % COUT;
    const bool isxyz = (co < 3);

    {
        const float* srcf =
            (co == 0) ? (g_px + (size_t)b * NN) :
            (co == 1) ? (g_py + (size_t)b * NN) :
            (co == 2) ? (g_pz + (size_t)b * NN) :
                        (feats + ((size_t)b * CC + (co - 3)) * NN);
        uint32_t rbase;
        asm("{ .reg .u64 t; cvta.to.shared.u64 t, %1; cvt.u32.u64 %0, t; }"
            : "=r"(rbase) : "l"(row));
        #pragma unroll
        for (int k = 0; k < 8; ++k) {
            const int i = threadIdx.x + k * 512;
            cp_async16(rbase + 16u * i, (const float4*)srcf + i);
        }
        asm volatile("cp.async.commit_group;\n" ::: "memory");
        asm volatile("cp.async.wait_group 0;\n" ::: "memory");
    }
    __syncthreads();

    const int4*  idx4 = (const int4*)(g_idx + (size_t)b * SS * KK);
    float4*      out4 = (float4*)(out + (size_t)plane * SS * KK);
    const float* cbase = centers + (size_t)b * SS * 3 + co;

    const int base = quart * 4096;      // this block: float4s [base, base+4096)
    #pragma unroll 1
    for (int ii = 0; ii < 2; ++ii) {
        const int i0 = base + ii * 2048 + threadIdx.x;
        const int i1 = i0 + 512, i2 = i0 + 1024, i3 = i0 + 1536;

        const int4 d0 = __ldg(idx4 + i0);
        const int4 d1 = __ldg(idx4 + i1);
        const int4 d2 = __ldg(idx4 + i2);
        const int4 d3 = __ldg(idx4 + i3);

        float4 v0, v1, v2, v3;
        v0.x = row[d0.x]; v0.y = row[d0.y]; v0.z = row[d0.z]; v0.w = row[d0.w];
        v1.x = row[d1.x]; v1.y = row[d1.y]; v1.z = row[d1.z]; v1.w = row[d1.w];
        v2.x = row[d2.x]; v2.y = row[d2.y]; v2.z = row[d2.z]; v2.w = row[d2.w];
        v3.x = row[d3.x]; v3.y = row[d3.y]; v3.z = row[d3.z]; v3.w = row[d3.w];

        if (isxyz) {
            const float c0 = __ldg(cbase + 3 * (i0 >> 3));
            const float c1 = __ldg(cbase + 3 * (i1 >> 3));
            const float c2 = __ldg(cbase + 3 * (i2 >> 3));
            const float c3 = __ldg(cbase + 3 * (i3 >> 3));
            v0.x -= c0; v0.y -= c0; v0.z -= c0; v0.w -= c0;
            v1.x -= c1; v1.y -= c1; v1.z -= c1; v1.w -= c1;
            v2.x -= c2; v2.y -= c2; v2.z -= c2; v2.w -= c2;
            v3.x -= c3; v3.y -= c3; v3.z -= c3; v3.w -= c3;
        }

        out4[i0] = v0;
        out4[i1] = v1;
        out4[i2] = v2;
        out4[i3] = v3;
    }
}

// ---------------------------------------------------------------------------
extern "C" void kernel_launch(void* const* d_in, const int* in_sizes, int n_in,
                              void* d_out, int out_size)
{
    const float* points  = (const float*)d_in[0];  // 8*16384*3
    const float* centers = (const float*)d_in[1];  // 8*2048*3
    const float* feats   = (const float*)d_in[2];  // 8*64*16384
    float* out = (float*)d_out;                    // 8*67*2048*32

    (void)in_sizes; (void)n_in; (void)out_size;

    static_assert(NN * sizeof(float) == 65536, "row size");
    cudaFuncSetAttribute(gather_kernel,
                         cudaFuncAttributeMaxDynamicSharedMemorySize,
                         NN * (int)sizeof(float));

    transpose_kernel<<<BB * NN / 128, 32>>>((const float4*)points);
    ball_query_kernel<<<BB * SS / 8, 256>>>(centers);
    gather_kernel<<<BB * COUT * 4, 512, NN * sizeof(float)>>>(centers, feats, out);
}

// round 17
// speedup vs baseline: 1.0472x; 1.0472x over previous
#include <cuda_runtime.h>
#include <stdint.h>

#define BB 8
#define NN 16384
#define SS 2048
#define CC 64
#define KK 32
#define COUT (3 + CC)      // 67
#define NG2 (NN / 256)     // 64 iterations of 256 points

typedef unsigned long long u64;

// Scratch (no cudaMalloc allowed).
__device__ __align__(16) int   g_idx[BB * SS * KK];
__device__ __align__(16) float g_px[BB * NN];
__device__ __align__(16) float g_py[BB * NN];
__device__ __align__(16) float g_pz[BB * NN];

__device__ __forceinline__ void cp_async16(uint32_t dst_smem, const void* src) {
    asm volatile("cp.async.cg.shared.global [%0], [%1], 16;\n"
                 :: "r"(dst_smem), "l"(src) : "memory");
}

// ---- packed f32x2 helpers (sm_100a+): per-component round-to-nearest,
// bit-identical to __fadd_rn/__fmul_rn on each half. ----
__device__ __forceinline__ u64 addx2(u64 a, u64 b) {
    u64 r; asm("add.rn.f32x2 %0, %1, %2;" : "=l"(r) : "l"(a), "l"(b)); return r;
}
__device__ __forceinline__ u64 mulx2(u64 a, u64 b) {
    u64 r; asm("mul.rn.f32x2 %0, %1, %2;" : "=l"(r) : "l"(a), "l"(b)); return r;
}
__device__ __forceinline__ u64 pack2(float lo, float hi) {
    u64 r; asm("mov.b64 %0, {%1, %2};" : "=l"(r) : "f"(lo), "f"(hi)); return r;
}
__device__ __forceinline__ void unpack2(u64 v, float& lo, float& hi) {
    asm("mov.b64 {%0, %1}, %2;" : "=f"(lo), "=f"(hi) : "l"(v));
}
// d2 for a pair of points given packed component diffs (already p-c):
__device__ __forceinline__ u64 d2x2(u64 ex, u64 ey, u64 ez) {
    return addx2(addx2(mulx2(ex, ex), mulx2(ey, ey)), mulx2(ez, ez));
}

// ---------------------------------------------------------------------------
// Kernel 0: AoS (B,N,3) -> SoA px/py/pz. 1024 blocks x 32 threads.
// ---------------------------------------------------------------------------
__global__ __launch_bounds__(32) void transpose_kernel(
    const float4* __restrict__ pts4)    // (B*N*3)/4 float4s
{
    __shared__ float4 sm[96];           // 128 points * 3 floats
    const int tid = threadIdx.x;        // 0..31
    const int blk = blockIdx.x;         // 0..1023

    #pragma unroll
    for (int k = 0; k < 3; ++k)
        sm[tid + k * 32] = __ldg(pts4 + (size_t)blk * 96 + tid + k * 32);
    __syncwarp();

    const float* sf = (const float*)sm;
    const int lp = 12 * tid;            // local float base for points 4t..4t+3
    float4 vx, vy, vz;
    vx.x = sf[lp + 0]; vy.x = sf[lp + 1];  vz.x = sf[lp + 2];
    vx.y = sf[lp + 3]; vy.y = sf[lp + 4];  vz.y = sf[lp + 5];
    vx.z = sf[lp + 6]; vy.z = sf[lp + 7];  vz.z = sf[lp + 8];
    vx.w = sf[lp + 9]; vy.w = sf[lp + 10]; vz.w = sf[lp + 11];

    const int o = blk * 32 + tid;       // float4 index into SoA arrays
    ((float4*)g_px)[o] = vx;
    ((float4*)g_py)[o] = vy;
    ((float4*)g_pz)[o] = vz;
}

// ---------------------------------------------------------------------------
// Kernel 1: warp-per-center ball query, 256 points/iter, f32x2 packed math.
// LDG.128 delivers natural point-pairs (ulonglong2 view, zero pack cost).
// Per pair: 3 add.f32x2 (p + (-c)) + 3 mul + 2 add — each half bit-identical
// to the scalar __fadd_rn/__fmul_rn sequence ((dx*dx+dy*dy)+dz*dz), and
// (p-c)^2 == (c-p)^2 exactly. 8 ballots (R9-proven prefix), warp-uniform
// early exit. Index order: j = g*256 + sub*128 + 4*lane + c (ascending).
// Semantics: smallest 32 indices j with |c-p_j|^2 < 0.04 (ascending),
// padded with the first found index, or 0 if none found.
// ---------------------------------------------------------------------------
__global__ __launch_bounds__(256) void ball_query_kernel(
    const float* __restrict__ centers)   // (B, S, 3)
{
    const int wid  = threadIdx.x >> 5;
    const int lane = threadIdx.x & 31;
    const int gw   = blockIdx.x * 8 + wid;   // center id = b*S + s
    const int b    = gw >> 11;               // / SS

    const float* cptr = centers + (size_t)gw * 3;
    const float cx = __ldg(cptr + 0);
    const float cy = __ldg(cptr + 1);
    const float cz = __ldg(cptr + 2);
    const u64 ncx = pack2(-cx, -cx);
    const u64 ncy = pack2(-cy, -cy);
    const u64 ncz = pack2(-cz, -cz);

    __shared__ int sel[8][KK];

    const ulonglong2* px2 = (const ulonglong2*)(g_px + (size_t)b * NN);
    const ulonglong2* py2 = (const ulonglong2*)(g_py + (size_t)b * NN);
    const ulonglong2* pz2 = (const ulonglong2*)(g_pz + (size_t)b * NN);

    const float R2 = 0.04f;
    const unsigned below = (1u << lane) - 1u;

    int cnt = 0;

    // prefetch iteration 0: u64x2 index g*64 + lane (sub0) and +32 (sub1)
    ulonglong2 ax0 = __ldg(px2 + lane),      ay0 = __ldg(py2 + lane),      az0 = __ldg(pz2 + lane);
    ulonglong2 ax1 = __ldg(px2 + 32 + lane), ay1 = __ldg(py2 + 32 + lane), az1 = __ldg(pz2 + 32 + lane);

    for (int g = 0; g < NG2; ++g) {
        ulonglong2 bx0 = make_ulonglong2(0ull, 0ull), by0 = bx0, bz0 = bx0;
        ulonglong2 bx1 = bx0, by1 = bx0, bz1 = bx0;
        if (g + 1 < NG2) {
            const int nf = (g + 1) * 64 + lane;
            bx0 = __ldg(px2 + nf);      by0 = __ldg(py2 + nf);      bz0 = __ldg(pz2 + nf);
            bx1 = __ldg(px2 + nf + 32); by1 = __ldg(py2 + nf + 32); bz1 = __ldg(pz2 + nf + 32);
        }

        // 4 point-pairs: (p0,p1),(p2,p3) of sub0; (p4,p5),(p6,p7) of sub1
        const u64 dA = d2x2(addx2(ax0.x, ncx), addx2(ay0.x, ncy), addx2(az0.x, ncz));
        const u64 dB = d2x2(addx2(ax0.y, ncx), addx2(ay0.y, ncy), addx2(az0.y, ncz));
        const u64 dC = d2x2(addx2(ax1.x, ncx), addx2(ay1.x, ncy), addx2(az1.x, ncz));
        const u64 dD = d2x2(addx2(ax1.y, ncx), addx2(ay1.y, ncy), addx2(az1.y, ncz));

        float q0,q1,q2,q3,q4,q5,q6,q7;
        unpack2(dA, q0, q1);
        unpack2(dB, q2, q3);
        unpack2(dC, q4, q5);
        unpack2(dD, q6, q7);

        const bool h0=q0<R2, h1=q1<R2, h2=q2<R2, h3=q3<R2;
        const bool h4=q4<R2, h5=q5<R2, h6=q6<R2, h7=q7<R2;
        const unsigned m0=__ballot_sync(0xffffffffu,h0), m1=__ballot_sync(0xffffffffu,h1);
        const unsigned m2=__ballot_sync(0xffffffffu,h2), m3=__ballot_sync(0xffffffffu,h3);
        const unsigned m4=__ballot_sync(0xffffffffu,h4), m5=__ballot_sync(0xffffffffu,h5);
        const unsigned m6=__ballot_sync(0xffffffffu,h6), m7=__ballot_sync(0xffffffffu,h7);

        const int t0 = __popc(m0)+__popc(m1)+__popc(m2)+__popc(m3);
        const int t1 = __popc(m4)+__popc(m5)+__popc(m6)+__popc(m7);

        // sub0: j = g*256 + 4*lane + c
        int p = cnt + __popc(m0&below)+__popc(m1&below)+__popc(m2&below)+__popc(m3&below);
        const int j0 = g * 256 + 4 * lane;
        if (h0) { if (p < KK) sel[wid][p] = j0 + 0; p++; }
        if (h1) { if (p < KK) sel[wid][p] = j0 + 1; p++; }
        if (h2) { if (p < KK) sel[wid][p] = j0 + 2; p++; }
        if (h3) { if (p < KK) sel[wid][p] = j0 + 3; p++; }
        // sub1: j = g*256 + 128 + 4*lane + c (all indices > sub0's)
        int q = cnt + t0 + __popc(m4&below)+__popc(m5&below)+__popc(m6&below)+__popc(m7&below);
        const int j1 = j0 + 128;
        if (h4) { if (q < KK) sel[wid][q] = j1 + 0; q++; }
        if (h5) { if (q < KK) sel[wid][q] = j1 + 1; q++; }
        if (h6) { if (q < KK) sel[wid][q] = j1 + 2; q++; }
        if (h7) { if (q < KK) sel[wid][q] = j1 + 3; q++; }

        cnt += t0 + t1;
        if (cnt >= KK) break;   // warp-uniform

        ax0 = bx0; ay0 = by0; az0 = bz0;
        ax1 = bx1; ay1 = by1; az1 = bz1;
    }
    __syncwarp();

    int v;
    if (cnt == 0) {
        v = 0;
    } else {
        const int first = sel[wid][0];
        v = (lane < cnt) ? sel[wid][lane] : first;
    }
    g_idx[(size_t)gw * KK + lane] = v;
}

// ---------------------------------------------------------------------------
// Kernel 2: gather (best-measured config). Four chunks per (b, out-channel)
// plane, 512 threads. Stage 64KB row via cp.async, gather via LDS, coalesced
// float4 stores.
// ---------------------------------------------------------------------------
__global__ __launch_bounds__(512) void gather_kernel(
    const float* __restrict__ centers,  // (B, S, 3)
    const float* __restrict__ feats,    // (B, C, N)
    float* __restrict__ out)            // (B, 67, S, K)
{
    extern __shared__ float row[];      // NN floats = 64KB

    const int chunk = blockIdx.x;       // 0 .. B*67*4-1
    const int plane = chunk >> 2;
    const int quart = chunk & 3;
    const int b  = plane / COUT;
    const int co = plane % COUT;
    const bool isxyz = (co < 3);

    {
        const float* srcf =
            (co == 0) ? (g_px + (size_t)b * NN) :
            (co == 1) ? (g_py + (size_t)b * NN) :
            (co == 2) ? (g_pz + (size_t)b * NN) :
                        (feats + ((size_t)b * CC + (co - 3)) * NN);
        uint32_t rbase;
        asm("{ .reg .u64 t; cvta.to.shared.u64 t, %1; cvt.u32.u64 %0, t; }"
            : "=r"(rbase) : "l"(row));
        #pragma unroll
        for (int k = 0; k < 8; ++k) {
            const int i = threadIdx.x + k * 512;
            cp_async16(rbase + 16u * i, (const float4*)srcf + i);
        }
        asm volatile("cp.async.commit_group;\n" ::: "memory");
        asm volatile("cp.async.wait_group 0;\n" ::: "memory");
    }
    __syncthreads();

    const int4*  idx4 = (const int4*)(g_idx + (size_t)b * SS * KK);
    float4*      out4 = (float4*)(out + (size_t)plane * SS * KK);
    const float* cbase = centers + (size_t)b * SS * 3 + co;

    const int base = quart * 4096;      // this block: float4s [base, base+4096)
    #pragma unroll 1
    for (int ii = 0; ii < 2; ++ii) {
        const int i0 = base + ii * 2048 + threadIdx.x;
        const int i1 = i0 + 512, i2 = i0 + 1024, i3 = i0 + 1536;

        const int4 d0 = __ldg(idx4 + i0);
        const int4 d1 = __ldg(idx4 + i1);
        const int4 d2 = __ldg(idx4 + i2);
        const int4 d3 = __ldg(idx4 + i3);

        float4 v0, v1, v2, v3;
        v0.x = row[d0.x]; v0.y = row[d0.y]; v0.z = row[d0.z]; v0.w = row[d0.w];
        v1.x = row[d1.x]; v1.y = row[d1.y]; v1.z = row[d1.z]; v1.w = row[d1.w];
        v2.x = row[d2.x]; v2.y = row[d2.y]; v2.z = row[d2.z]; v2.w = row[d2.w];
        v3.x = row[d3.x]; v3.y = row[d3.y]; v3.z = row[d3.z]; v3.w = row[d3.w];

        if (isxyz) {
            const float c0 = __ldg(cbase + 3 * (i0 >> 3));
            const float c1 = __ldg(cbase + 3 * (i1 >> 3));
            const float c2 = __ldg(cbase + 3 * (i2 >> 3));
            const float c3 = __ldg(cbase + 3 * (i3 >> 3));
            v0.x -= c0; v0.y -= c0; v0.z -= c0; v0.w -= c0;
            v1.x -= c1; v1.y -= c1; v1.z -= c1; v1.w -= c1;
            v2.x -= c2; v2.y -= c2; v2.z -= c2; v2.w -= c2;
            v3.x -= c3; v3.y -= c3; v3.z -= c3; v3.w -= c3;
        }

        out4[i0] = v0;
        out4[i1] = v1;
        out4[i2] = v2;
        out4[i3] = v3;
    }
}

// ---------------------------------------------------------------------------
extern "C" void kernel_launch(void* const* d_in, const int* in_sizes, int n_in,
                              void* d_out, int out_size)
{
    const float* points  = (const float*)d_in[0];  // 8*16384*3
    const float* centers = (const float*)d_in[1];  // 8*2048*3
    const float* feats   = (const float*)d_in[2];  // 8*64*16384
    float* out = (float*)d_out;                    // 8*67*2048*32

    (void)in_sizes; (void)n_in; (void)out_size;

    static_assert(NN * sizeof(float) == 65536, "row size");
    cudaFuncSetAttribute(gather_kernel,
                         cudaFuncAttributeMaxDynamicSharedMemorySize,
                         NN * (int)sizeof(float));

    transpose_kernel<<<BB * NN / 128, 32>>>((const float4*)points);
    ball_query_kernel<<<BB * SS / 8, 256>>>(centers);
    gather_kernel<<<BB * COUT * 4, 512, NN * sizeof(float)>>>(centers, feats, out);
}